// round 15
// baseline (speedup 1.0000x reference)
#include <cuda_runtime.h>
#include <cuda_fp16.h>
#include <math.h>
#include <cstdint>

#define D_MODEL 1024
#define NHEAD   16
#define D_K     64
#define BATCH   4
#define SEQ     2048
#define M_TOT   (BATCH * SEQ)   // 8192

// ---------------- scratch (device globals: allocation-free rule) ----------------
__device__ __half g_X0 [M_TOT * D_MODEL];
__device__ __half g_X1 [M_TOT * D_MODEL];
__device__ __half g_X2 [M_TOT * D_MODEL];
__device__ __half g_Q16[M_TOT * D_MODEL];
__device__ __half g_K16[M_TOT * D_MODEL];
__device__ __half g_VT [M_TOT * D_MODEL];
__device__ __half g_CH [M_TOT * D_MODEL];
__device__ __half g_CL [M_TOT * D_MODEL];
__device__ __half g_W0 [D_MODEL * D_MODEL];
__device__ __half g_W1 [D_MODEL * D_MODEL];
__device__ __half g_W2 [D_MODEL * D_MODEL];
__device__ __half g_W3 [D_MODEL * D_MODEL];

// ====================== helpers ======================
__device__ __forceinline__ uint32_t smem_u32(const void* p) {
    uint32_t a;
    asm("{ .reg .u64 t; cvta.to.shared.u64 t, %1; cvt.u32.u64 %0, t; }" : "=r"(a) : "l"(p));
    return a;
}
__device__ __forceinline__ void ldsm4(uint32_t* r, uint32_t addr) {
    asm volatile("ldmatrix.sync.aligned.m8n8.x4.shared.b16 {%0,%1,%2,%3}, [%4];"
        : "=r"(r[0]), "=r"(r[1]), "=r"(r[2]), "=r"(r[3]) : "r"(addr));
}
__device__ __forceinline__ void mma_f16(float* c, const uint32_t* a, const uint32_t* b) {
    asm volatile("mma.sync.aligned.m16n8k16.row.col.f32.f16.f16.f32 "
        "{%0,%1,%2,%3}, {%4,%5,%6,%7}, {%8,%9}, {%0,%1,%2,%3};"
        : "+f"(c[0]), "+f"(c[1]), "+f"(c[2]), "+f"(c[3])
        : "r"(a[0]), "r"(a[1]), "r"(a[2]), "r"(a[3]), "r"(b[0]), "r"(b[1]));
}
__device__ __forceinline__ float ex2f(float x) {
    float r;
    asm("ex2.approx.f32 %0, %1;" : "=f"(r) : "f"(x));
    return r;
}
__device__ __forceinline__ uint32_t pack_h(float x, float y) {
    __half2 h = __floats2half2_rn(x, y);
    return *(uint32_t*)&h;
}
__device__ __forceinline__ void store_hilo(__half* H, __half* L, size_t off, float x, float y) {
    __half hx = __float2half_rn(x), hy = __float2half_rn(y);
    __half lx = __float2half_rn(x - __half2float(hx));
    __half ly = __float2half_rn(y - __half2float(hy));
    *(__half2*)(H + off) = __halves2half2(hx, hy);
    *(__half2*)(L + off) = __halves2half2(lx, ly);
}
#define CP_ASYNC16(s, g) asm volatile("cp.async.cg.shared.global [%0], [%1], 16;" :: "r"(s), "l"(g) : "memory")
#define CP_COMMIT()      asm volatile("cp.async.commit_group;" ::: "memory")
#define CP_WAIT1()       asm volatile("cp.async.wait_group 1;" ::: "memory")
#define CP_WAIT0()       asm volatile("cp.async.wait_group 0;" ::: "memory")

// =================================================================================
// converts
// =================================================================================
struct ConvNArgs { const float* src[4]; __half* dst[4]; };

__global__ void convN_kernel(ConvNArgs a, int n)
{
    const float* x = a.src[blockIdx.z];
    __half* o = a.dst[blockIdx.z];
    int idx = (blockIdx.x * blockDim.x + threadIdx.x) * 4;
    if (idx >= n) return;
    float4 v = *(const float4*)(x + idx);
    *(__half2*)(o + idx)     = __floats2half2_rn(v.x, v.y);
    *(__half2*)(o + idx + 2) = __floats2half2_rn(v.z, v.w);
}

// =================================================================================
// 4-warp GEMM core: CTA 128x128, BK=64, warp tile 64x64 (warp grid 2x2). 2 CTAs/SM.
// =================================================================================
#define G_ROWB   144
#define G_T128   (128 * G_ROWB)         // 18432

template<int NA>
__device__ __forceinline__ void gemm_load_stage(
    uint32_t sb, int tid,
    const __half* srcA0, const __half* srcA1, const __half* srcB,
    int st, int k0)
{
    constexpr int STAGE_B = (NA + 1) * G_T128;
    constexpr int NCH = (NA * 128 + 128) * 8;
#pragma unroll
    for (int i = 0; i < NCH / 128; i++) {
        const int c = tid + i * 128;
        const int row = c >> 3, ch = c & 7;
        const __half* g;
        uint32_t soff;
        if (row < 128) {
            g = srcA0 + (size_t)row * 1024;
            soff = (uint32_t)row * G_ROWB;
        } else if (NA == 2 && row < 256) {
            g = srcA1 + (size_t)(row - 128) * 1024;
            soff = G_T128 + (uint32_t)(row - 128) * G_ROWB;
        } else {
            const int br = row - NA * 128;
            g = srcB + (size_t)br * 1024;
            soff = NA * G_T128 + (uint32_t)br * G_ROWB;
        }
        CP_ASYNC16(sb + st * STAGE_B + soff + ch * 16, (const void*)(g + k0 + ch * 8));
    }
}

template<int NA>
__device__ __forceinline__ void gemm_compute_stage(
    uint32_t sb, int warp_m, int warp_n, uint32_t a_off, uint32_t b_off,
    int st, float acc[4][8][4])
{
    constexpr int STAGE_B = (NA + 1) * G_T128;
    const uint32_t s   = sb + st * STAGE_B;
    const uint32_t aB0 = s + (uint32_t)(warp_m * 64) * G_ROWB;
    const uint32_t aB1 = s + G_T128 + (uint32_t)(warp_m * 64) * G_ROWB;
    const uint32_t bB  = s + NA * G_T128 + (uint32_t)(warp_n * 64) * G_ROWB;
#pragma unroll
    for (int ks = 0; ks < 4; ks++) {
        uint32_t ah[4][4], al[4][4], bb[4][4];
#pragma unroll
        for (int mt = 0; mt < 4; mt++) {
            ldsm4(ah[mt], aB0 + (uint32_t)(mt * 16) * G_ROWB + ks * 32 + a_off);
            if (NA == 2)
                ldsm4(al[mt], aB1 + (uint32_t)(mt * 16) * G_ROWB + ks * 32 + a_off);
        }
#pragma unroll
        for (int p = 0; p < 4; p++)
            ldsm4(bb[p], bB + (uint32_t)(p * 16) * G_ROWB + ks * 32 + b_off);
#pragma unroll
        for (int mt = 0; mt < 4; mt++)
#pragma unroll
            for (int nt = 0; nt < 8; nt++) {
                float* c = acc[mt][nt];
                const uint32_t* bp = &bb[nt >> 1][(nt & 1) * 2];
                mma_f16(c, ah[mt], bp);
                if (NA == 2) mma_f16(c, al[mt], bp);
            }
    }
}

// ---- fused QKV projection; V channel writes transposed (VT) directly ----
struct ProjOne {
    const __half *A, *W;
    const float* bias;
    __half *O;
    float scale;
    int vtrans;     // 0: row-major fp16 out; 1: write O as VT[(b*16+h)*64+d][s]
};
struct Proj3Args { ProjOne p[3]; };

__global__ __launch_bounds__(128, 2)
void proj3_kernel(Proj3Args args)
{
    extern __shared__ __align__(128) char smem[];
    const ProjOne P = args.p[blockIdx.z];
    const uint32_t sb = smem_u32(smem);
    const int tid = threadIdx.x, lane = tid & 31, wid = tid >> 5;
    const int row0 = blockIdx.y * 128, col0 = blockIdx.x * 128;
    const int warp_m = wid >> 1, warp_n = wid & 1;
    const int la = lane & 7, lb8 = (lane >> 3) & 1, lb16 = lane >> 4;
    const uint32_t a_off = (uint32_t)((la + lb8 * 8) * G_ROWB + lb16 * 16);
    const uint32_t b_off = (uint32_t)((la + lb16 * 8) * G_ROWB + lb8 * 16);

    const __half* srcA = P.A + (size_t)row0 * 1024;
    const __half* srcB = P.W + (size_t)col0 * 1024;

    float acc[4][8][4];
#pragma unroll
    for (int a = 0; a < 4; a++)
#pragma unroll
        for (int b = 0; b < 8; b++)
#pragma unroll
            for (int c = 0; c < 4; c++) acc[a][b][c] = 0.f;

    gemm_load_stage<1>(sb, tid, srcA, nullptr, srcB, 0, 0);   CP_COMMIT();
    gemm_load_stage<1>(sb, tid, srcA, nullptr, srcB, 1, 64);  CP_COMMIT();
    for (int c = 0; c < 16; c++) {
        CP_WAIT1();
        __syncthreads();
        gemm_compute_stage<1>(sb, warp_m, warp_n, a_off, b_off, c % 3, acc);
        if (c + 2 < 16)
            gemm_load_stage<1>(sb, tid, srcA, nullptr, srcB, (c + 2) % 3, (c + 2) * 64);
        CP_COMMIT();
    }

    const int r_base = row0 + warp_m * 64, c_base = col0 + warp_n * 64;
#pragma unroll
    for (int mt = 0; mt < 4; mt++) {
        const int r0 = r_base + mt * 16 + (lane >> 2);
#pragma unroll
        for (int nt = 0; nt < 8; nt++) {
            const int cc = c_base + nt * 8 + (lane & 3) * 2;
            const float b0 = __ldg(P.bias + cc), b1 = __ldg(P.bias + cc + 1);
            const float v00 = (acc[mt][nt][0] + b0) * P.scale;
            const float v01 = (acc[mt][nt][1] + b1) * P.scale;
            const float v10 = (acc[mt][nt][2] + b0) * P.scale;
            const float v11 = (acc[mt][nt][3] + b1) * P.scale;
            if (!P.vtrans) {
                *(__half2*)(P.O + (size_t)r0 * 1024 + cc)      = __floats2half2_rn(v00, v01);
                *(__half2*)(P.O + (size_t)(r0 + 8) * 1024 + cc) = __floats2half2_rn(v10, v11);
            } else {
                // VT[(b*16+h)*64 + d][s]; r = b*2048 + s; cc = h*64 + d
                const int h = cc >> 6, d = cc & 63;
#pragma unroll
                for (int rr = 0; rr < 2; rr++) {
                    const int r = r0 + rr * 8;
                    const int b = r >> 11, s = r & 2047;
                    const size_t base = ((size_t)((b * 16 + h) * 64 + d)) * 2048 + s;
                    P.O[base]        = __float2half_rn(rr ? v10 : v00);
                    P.O[base + 2048] = __float2half_rn(rr ? v11 : v01);   // d+1 row
                }
            }
        }
    }
}

// ---- output projection: C 2-term x W 1-term, fp32 out. 2-stage pipeline. ----
__global__ __launch_bounds__(128, 2)
void gemmF_kernel(const __half* __restrict__ Ch, const __half* __restrict__ Cl,
                  const __half* __restrict__ W,
                  const float* __restrict__ bias, float* __restrict__ C)
{
    extern __shared__ __align__(128) char smem[];
    const uint32_t sb = smem_u32(smem);
    const int tid = threadIdx.x, lane = tid & 31, wid = tid >> 5;
    const int row0 = blockIdx.y * 128, col0 = blockIdx.x * 128;
    const int warp_m = wid >> 1, warp_n = wid & 1;
    const int la = lane & 7, lb8 = (lane >> 3) & 1, lb16 = lane >> 4;
    const uint32_t a_off = (uint32_t)((la + lb8 * 8) * G_ROWB + lb16 * 16);
    const uint32_t b_off = (uint32_t)((la + lb16 * 8) * G_ROWB + lb8 * 16);

    const __half* srcA0 = Ch + (size_t)row0 * 1024;
    const __half* srcA1 = Cl + (size_t)row0 * 1024;
    const __half* srcB  = W  + (size_t)col0 * 1024;

    float acc[4][8][4];
#pragma unroll
    for (int a = 0; a < 4; a++)
#pragma unroll
        for (int b = 0; b < 8; b++)
#pragma unroll
            for (int c = 0; c < 4; c++) acc[a][b][c] = 0.f;

    gemm_load_stage<2>(sb, tid, srcA0, srcA1, srcB, 0, 0);   CP_COMMIT();
    for (int c = 0; c < 16; c++) {
        CP_WAIT0();
        __syncthreads();
        if (c + 1 < 16) {
            gemm_load_stage<2>(sb, tid, srcA0, srcA1, srcB, (c + 1) & 1, (c + 1) * 64);
            CP_COMMIT();
        }
        gemm_compute_stage<2>(sb, warp_m, warp_n, a_off, b_off, c & 1, acc);
        __syncthreads();
    }

    const int r_base = row0 + warp_m * 64, c_base = col0 + warp_n * 64;
#pragma unroll
    for (int mt = 0; mt < 4; mt++) {
        const int r = r_base + mt * 16 + (lane >> 2);
#pragma unroll
        for (int nt = 0; nt < 8; nt++) {
            const int cc = c_base + nt * 8 + (lane & 3) * 2;
            const float b0 = __ldg(bias + cc), b1 = __ldg(bias + cc + 1);
            float2 o0, o1;
            o0.x = acc[mt][nt][0] + b0; o0.y = acc[mt][nt][1] + b1;
            o1.x = acc[mt][nt][2] + b0; o1.y = acc[mt][nt][3] + b1;
            *(float2*)(C + (size_t)r * 1024 + cc)       = o0;
            *(float2*)(C + (size_t)(r + 8) * 1024 + cc) = o1;
        }
    }
}

// =================================================================================
// Flash attention v2: 4 warps / 128 threads, warp m-tile 16, q-tile 64/CTA,
// kv-tile 128/iter (16 iters). Grid 2048 CTAs (tail ~1.5%). ex2 softmax.
// Stage: K[128 x 144B] + VT[64 x 272B]. 3-stage ring.
// =================================================================================
#define AK_STRIDE 144
#define AV_STRIDE 272
#define AK_TILE   (128 * AK_STRIDE)     // 18432
#define AV_TILE   (64 * AV_STRIDE)      // 17408
#define A_STAGE   (AK_TILE + AV_TILE)   // 35840
#define A_SMEM_TOT (3 * A_STAGE)        // 107520

__global__ __launch_bounds__(128, 2)
void attention_mma_kernel(const __half* __restrict__ Q16,
                          const __half* __restrict__ K16, const __half* __restrict__ VT,
                          __half* __restrict__ CH, __half* __restrict__ CL)
{
    extern __shared__ __align__(128) char smem[];
    const uint32_t sb = smem_u32(smem);
    const int tid  = threadIdx.x;
    const int lane = tid & 31, wid = tid >> 5;   // wid 0..3
    const int bh = blockIdx.y;
    const int b = bh >> 4, h = bh & 15;
    const int q0 = blockIdx.x * 64;

    const int la   = lane & 7;
    const int lb8  = (lane >> 3) & 1;
    const int lb16 = lane >> 4;
    const uint32_t a_off  = (uint32_t)((la + lb8 * 8) * AK_STRIDE + lb16 * 16);
    const uint32_t bK_off = (uint32_t)((la + lb16 * 8) * AK_STRIDE + lb8 * 16);
    const uint32_t bV_off = (uint32_t)((la + lb16 * 8) * AV_STRIDE + lb8 * 16);

    // ---- stage Q (64 rows x 64 d) and move to registers ----
    {
#pragma unroll
        for (int i = 0; i < 4; i++) {
            int c = tid + i * 128;            // 0..511
            int r = c >> 3, ch = c & 7;
            const size_t g = (size_t)(b * SEQ + q0 + r) * D_MODEL + h * 64 + ch * 8;
            CP_ASYNC16(sb + r * AK_STRIDE + ch * 16, (const void*)(Q16 + g));
        }
        CP_COMMIT();
        CP_WAIT0();
        __syncthreads();
    }
    uint32_t qh[4][4];
#pragma unroll
    for (int ks = 0; ks < 4; ks++)
        ldsm4(qh[ks], sb + (uint32_t)(wid * 16) * AK_STRIDE + ks * 32 + a_off);
    __syncthreads();

    // ---- KV loader: K 1024 chunks + VT 1024 chunks; 16 per thread ----
    auto load_stage = [&](int st, int kv0) {
#pragma unroll
        for (int i = 0; i < 16; i++) {
            const int c = tid + i * 128;
            const __half* g;
            uint32_t soff;
            if (c < 1024) {
                const int row = c >> 3, ch = c & 7;
                g = K16 + (size_t)(b * SEQ + kv0 + row) * D_MODEL + h * 64 + ch * 8;
                soff = (uint32_t)row * AK_STRIDE + ch * 16;
            } else {
                const int c2 = c - 1024;
                const int row = c2 >> 4, ch = c2 & 15;
                g = VT + (size_t)(bh * 64 + row) * SEQ + kv0 + ch * 8;
                soff = AK_TILE + (uint32_t)row * AV_STRIDE + ch * 16;
            }
            CP_ASYNC16(sb + st * A_STAGE + soff, (const void*)g);
        }
    };

    load_stage(0, 0);   CP_COMMIT();
    load_stage(1, 128); CP_COMMIT();

    float o[8][4];
#pragma unroll
    for (int t = 0; t < 8; t++)
#pragma unroll
        for (int j = 0; j < 4; j++) o[t][j] = 0.f;
    float m_r[2] = {-1e30f, -1e30f};
    float l_r[2] = {0.f, 0.f};

    for (int it = 0; it < 16; it++) {
        CP_WAIT1();
        __syncthreads();
        const uint32_t st = sb + (it % 3) * A_STAGE;

        // ---- S = Q K^T (kv 128; log2-domain scores) ----
        float s[16][4];
#pragma unroll
        for (int t = 0; t < 16; t++)
#pragma unroll
            for (int j = 0; j < 4; j++) s[t][j] = 0.f;
#pragma unroll
        for (int ks = 0; ks < 4; ks++) {
#pragma unroll
            for (int np = 0; np < 8; np++) {
                uint32_t k4[4];
                const uint32_t base = (uint32_t)(np * 16) * AK_STRIDE + ks * 32 + bK_off;
                ldsm4(k4, st + base);
                mma_f16(s[2 * np],     qh[ks], k4);
                mma_f16(s[2 * np + 1], qh[ks], k4 + 2);
            }
        }

        // ---- online softmax (2 rows per thread) via ex2 ----
#pragma unroll
        for (int r = 0; r < 2; r++) {
            float mx = s[0][2 * r];
#pragma unroll
            for (int t = 0; t < 16; t++) {
                mx = fmaxf(mx, s[t][2 * r]);
                mx = fmaxf(mx, s[t][2 * r + 1]);
            }
            mx = fmaxf(mx, __shfl_xor_sync(0xffffffffu, mx, 1));
            mx = fmaxf(mx, __shfl_xor_sync(0xffffffffu, mx, 2));
            float mn = fmaxf(m_r[r], mx);
            float al = ex2f(m_r[r] - mn);
            m_r[r] = mn;
            float sum = 0.f;
#pragma unroll
            for (int t = 0; t < 16; t++) {
                float p0 = ex2f(s[t][2 * r]     - mn);
                float p1 = ex2f(s[t][2 * r + 1] - mn);
                s[t][2 * r] = p0; s[t][2 * r + 1] = p1;
                sum += p0 + p1;
            }
            sum += __shfl_xor_sync(0xffffffffu, sum, 1);
            sum += __shfl_xor_sync(0xffffffffu, sum, 2);
            l_r[r] = l_r[r] * al + sum;
#pragma unroll
            for (int t = 0; t < 8; t++) {
                o[t][2 * r] *= al; o[t][2 * r + 1] *= al;
            }
        }

        // ---- O += P V (k = 128 over 8 ks steps) ----
#pragma unroll
        for (int ks = 0; ks < 8; ks++) {
            const int t0 = 2 * ks, t1 = 2 * ks + 1;
            uint32_t pa[4];
            pa[0] = pack_h(s[t0][0], s[t0][1]);
            pa[1] = pack_h(s[t0][2], s[t0][3]);
            pa[2] = pack_h(s[t1][0], s[t1][1]);
            pa[3] = pack_h(s[t1][2], s[t1][3]);
#pragma unroll
            for (int np = 0; np < 4; np++) {
                uint32_t v4[4];
                const uint32_t base = (uint32_t)(np * 16) * AV_STRIDE + ks * 32 + bV_off;
                ldsm4(v4, st + AK_TILE + base);
                mma_f16(o[2 * np],     pa, v4);
                mma_f16(o[2 * np + 1], pa, v4 + 2);
            }
        }

        if (it + 2 < 16) load_stage((it + 2) % 3, (it + 2) * 128);
        CP_COMMIT();
    }

    // ---- epilogue: context hi/lo ----
    const float inv0 = 1.f / l_r[0];
    const float inv1 = 1.f / l_r[1];
    const int row0 = q0 + wid * 16 + (lane >> 2);
#pragma unroll
    for (int t = 0; t < 8; t++) {
        const int col = h * 64 + t * 8 + (lane & 3) * 2;
        store_hilo(CH, CL, (size_t)(b * SEQ + row0) * D_MODEL + col,
                   o[t][0] * inv0, o[t][1] * inv0);
        store_hilo(CH, CL, (size_t)(b * SEQ + row0 + 8) * D_MODEL + col,
                   o[t][2] * inv1, o[t][3] * inv1);
    }
}

// =================================================================================
// launch
// =================================================================================
extern "C" void kernel_launch(void* const* d_in, const int* in_sizes, int n_in,
                              void* d_out, int out_size)
{
    const float* x_q = (const float*)d_in[0];
    const float* x_k = (const float*)d_in[1];
    const float* x_v = (const float*)d_in[2];
    const float* wq  = (const float*)d_in[3];
    const float* bq  = (const float*)d_in[4];
    const float* wk  = (const float*)d_in[5];
    const float* bk  = (const float*)d_in[6];
    const float* wv  = (const float*)d_in[7];
    const float* bv  = (const float*)d_in[8];
    const float* wo  = (const float*)d_in[9];
    const float* bo  = (const float*)d_in[10];
    float* out = (float*)d_out;

    __half *x0, *x1, *x2, *q16, *k16, *vt, *ch, *cl;
    __half *w0, *w1, *w2, *w3;
    cudaGetSymbolAddress((void**)&x0,  g_X0);
    cudaGetSymbolAddress((void**)&x1,  g_X1);
    cudaGetSymbolAddress((void**)&x2,  g_X2);
    cudaGetSymbolAddress((void**)&q16, g_Q16);
    cudaGetSymbolAddress((void**)&k16, g_K16);
    cudaGetSymbolAddress((void**)&vt,  g_VT);
    cudaGetSymbolAddress((void**)&ch,  g_CH);
    cudaGetSymbolAddress((void**)&cl,  g_CL);
    cudaGetSymbolAddress((void**)&w0,  g_W0);
    cudaGetSymbolAddress((void**)&w1,  g_W1);
    cudaGetSymbolAddress((void**)&w2,  g_W2);
    cudaGetSymbolAddress((void**)&w3,  g_W3);

    static int attr_set = 0;
    const int proj_smem = 3 * 2 * G_T128;   // 110592
    const int gemf_smem = 2 * 3 * G_T128;   // 110592
    if (!attr_set) {
        cudaFuncSetAttribute(proj3_kernel,
                             cudaFuncAttributeMaxDynamicSharedMemorySize, proj_smem);
        cudaFuncSetAttribute(gemmF_kernel,
                             cudaFuncAttributeMaxDynamicSharedMemorySize, gemf_smem);
        cudaFuncSetAttribute(attention_mma_kernel,
                             cudaFuncAttributeMaxDynamicSharedMemorySize, A_SMEM_TOT);
        attr_set = 1;
    }

    const int NX = M_TOT * D_MODEL;
    const int NW = D_MODEL * D_MODEL;
    dim3 cb(256);

    // converts: inputs (z=3) + weights (z=4)
    {
        ConvNArgs cx; cx.src[0] = x_q; cx.src[1] = x_k; cx.src[2] = x_v; cx.src[3] = x_q;
        cx.dst[0] = x0; cx.dst[1] = x1; cx.dst[2] = x2; cx.dst[3] = x0;
        convN_kernel<<<dim3((NX / 4 + 255) / 256, 1, 3), cb>>>(cx, NX);
        ConvNArgs cw; cw.src[0] = wq; cw.src[1] = wk; cw.src[2] = wv; cw.src[3] = wo;
        cw.dst[0] = w0; cw.dst[1] = w1; cw.dst[2] = w2; cw.dst[3] = w3;
        convN_kernel<<<dim3((NW / 4 + 255) / 256, 1, 4), cb>>>(cw, NW);
    }

    // fused QKV projections; Q folds 1/sqrt(dk)*log2e; V writes transposed directly
    const float LOG2E = 1.4426950408889634f;
    Proj3Args pa;
    pa.p[0] = { x0, w0, bq, q16, 0.125f * LOG2E, 0 };
    pa.p[1] = { x1, w1, bk, k16, 1.0f, 0 };
    pa.p[2] = { x2, w2, bv, vt,  1.0f, 1 };
    proj3_kernel<<<dim3(8, 64, 3), 128, proj_smem>>>(pa);

    // attention (q-tile 64, kv-tile 128, ex2 softmax, context hi/lo out)
    attention_mma_kernel<<<dim3(SEQ / 64, BATCH * NHEAD), 128, A_SMEM_TOT>>>(
        q16, k16, vt, ch, cl);

    // output projection (C hi/lo x W, 2 products)
    gemmF_kernel<<<dim3(8, 64), 128, gemf_smem>>>(ch, cl, w3, bo, out);
}

// round 16
// speedup vs baseline: 1.0246x; 1.0246x over previous
#include <cuda_runtime.h>
#include <cuda_fp16.h>
#include <math.h>
#include <cstdint>

#define D_MODEL 1024
#define NHEAD   16
#define D_K     64
#define BATCH   4
#define SEQ     2048
#define M_TOT   (BATCH * SEQ)   // 8192

// ---------------- scratch (device globals: allocation-free rule) ----------------
__device__ __half g_X0 [M_TOT * D_MODEL];
__device__ __half g_X1 [M_TOT * D_MODEL];
__device__ __half g_X2 [M_TOT * D_MODEL];
__device__ __half g_Q16[M_TOT * D_MODEL];
__device__ __half g_K16[M_TOT * D_MODEL];
__device__ __half g_V16[M_TOT * D_MODEL];
__device__ __half g_VT [M_TOT * D_MODEL];
__device__ __half g_CH [M_TOT * D_MODEL];
__device__ __half g_CL [M_TOT * D_MODEL];
__device__ __half g_W0 [D_MODEL * D_MODEL];
__device__ __half g_W1 [D_MODEL * D_MODEL];
__device__ __half g_W2 [D_MODEL * D_MODEL];
__device__ __half g_W3 [D_MODEL * D_MODEL];

// ====================== helpers ======================
__device__ __forceinline__ uint32_t smem_u32(const void* p) {
    uint32_t a;
    asm("{ .reg .u64 t; cvta.to.shared.u64 t, %1; cvt.u32.u64 %0, t; }" : "=r"(a) : "l"(p));
    return a;
}
__device__ __forceinline__ void ldsm4(uint32_t* r, uint32_t addr) {
    asm volatile("ldmatrix.sync.aligned.m8n8.x4.shared.b16 {%0,%1,%2,%3}, [%4];"
        : "=r"(r[0]), "=r"(r[1]), "=r"(r[2]), "=r"(r[3]) : "r"(addr));
}
__device__ __forceinline__ void mma_f16(float* c, const uint32_t* a, const uint32_t* b) {
    asm volatile("mma.sync.aligned.m16n8k16.row.col.f32.f16.f16.f32 "
        "{%0,%1,%2,%3}, {%4,%5,%6,%7}, {%8,%9}, {%0,%1,%2,%3};"
        : "+f"(c[0]), "+f"(c[1]), "+f"(c[2]), "+f"(c[3])
        : "r"(a[0]), "r"(a[1]), "r"(a[2]), "r"(a[3]), "r"(b[0]), "r"(b[1]));
}
__device__ __forceinline__ uint32_t pack_h(float x, float y) {
    __half2 h = __floats2half2_rn(x, y);
    return *(uint32_t*)&h;
}
__device__ __forceinline__ void store_hilo(__half* H, __half* L, size_t off, float x, float y) {
    __half hx = __float2half_rn(x), hy = __float2half_rn(y);
    __half lx = __float2half_rn(x - __half2float(hx));
    __half ly = __float2half_rn(y - __half2float(hy));
    *(__half2*)(H + off) = __halves2half2(hx, hy);
    *(__half2*)(L + off) = __halves2half2(lx, ly);
}
#define CP_ASYNC16(s, g) asm volatile("cp.async.cg.shared.global [%0], [%1], 16;" :: "r"(s), "l"(g) : "memory")
#define CP_COMMIT()      asm volatile("cp.async.commit_group;" ::: "memory")
#define CP_WAIT1()       asm volatile("cp.async.wait_group 1;" ::: "memory")
#define CP_WAIT0()       asm volatile("cp.async.wait_group 0;" ::: "memory")

// =================================================================================
// converts
// =================================================================================
struct Conv3Args { const float* src[3]; __half* dst[3]; };

__global__ void conv3_kernel(Conv3Args a, int n)
{
    const float* x = a.src[blockIdx.z];
    __half* o = a.dst[blockIdx.z];
    int idx = (blockIdx.x * blockDim.x + threadIdx.x) * 4;
    if (idx >= n) return;
    float4 v = *(const float4*)(x + idx);
    *(__half2*)(o + idx)     = __floats2half2_rn(v.x, v.y);
    *(__half2*)(o + idx + 2) = __floats2half2_rn(v.z, v.w);
}

__global__ void conv1_kernel(const float* __restrict__ x, __half* __restrict__ o, int n)
{
    int idx = (blockIdx.x * blockDim.x + threadIdx.x) * 4;
    if (idx >= n) return;
    float4 v = *(const float4*)(x + idx);
    *(__half2*)(o + idx)     = __floats2half2_rn(v.x, v.y);
    *(__half2*)(o + idx + 2) = __floats2half2_rn(v.z, v.w);
}

// V transpose: V16 [b*S+s][h*64+d] -> VT [(b*16+h)*64+d][S]
__global__ void vtrans_kernel(const __half* __restrict__ V, __half* __restrict__ VT)
{
    __shared__ __half t[32][33];
    const int s0 = blockIdx.x * 32;
    const int d0 = blockIdx.y * 32;
    const int bh = blockIdx.z;
    const int b = bh >> 4, h = bh & 15;
    const int tid = threadIdx.x;
    const int cx = tid & 31, cy = tid >> 5;

#pragma unroll
    for (int i = 0; i < 4; i++) {
        int s = s0 + cy + i * 8;
        t[cy + i * 8][cx] = V[(size_t)(b * SEQ + s) * D_MODEL + h * 64 + d0 + cx];
    }
    __syncthreads();
#pragma unroll
    for (int i = 0; i < 4; i++) {
        int d = d0 + cy + i * 8;
        VT[(size_t)(bh * 64 + d) * SEQ + s0 + cx] = t[cx][cy + i * 8];
    }
}

// =================================================================================
// 4-warp GEMM core: CTA 128x128, BK=64, warp tile 64x64 (warp grid 2x2). 2 CTAs/SM.
// =================================================================================
#define G_ROWB   144
#define G_T128   (128 * G_ROWB)         // 18432

template<int NA>
__device__ __forceinline__ void gemm_load_stage(
    uint32_t sb, int tid,
    const __half* srcA0, const __half* srcA1, const __half* srcB,
    int st, int k0)
{
    constexpr int STAGE_B = (NA + 1) * G_T128;
    constexpr int NCH = (NA * 128 + 128) * 8;
#pragma unroll
    for (int i = 0; i < NCH / 128; i++) {
        const int c = tid + i * 128;
        const int row = c >> 3, ch = c & 7;
        const __half* g;
        uint32_t soff;
        if (row < 128) {
            g = srcA0 + (size_t)row * 1024;
            soff = (uint32_t)row * G_ROWB;
        } else if (NA == 2 && row < 256) {
            g = srcA1 + (size_t)(row - 128) * 1024;
            soff = G_T128 + (uint32_t)(row - 128) * G_ROWB;
        } else {
            const int br = row - NA * 128;
            g = srcB + (size_t)br * 1024;
            soff = NA * G_T128 + (uint32_t)br * G_ROWB;
        }
        CP_ASYNC16(sb + st * STAGE_B + soff + ch * 16, (const void*)(g + k0 + ch * 8));
    }
}

template<int NA>
__device__ __forceinline__ void gemm_compute_stage(
    uint32_t sb, int warp_m, int warp_n, uint32_t a_off, uint32_t b_off,
    int st, float acc[4][8][4])
{
    constexpr int STAGE_B = (NA + 1) * G_T128;
    const uint32_t s   = sb + st * STAGE_B;
    const uint32_t aB0 = s + (uint32_t)(warp_m * 64) * G_ROWB;
    const uint32_t aB1 = s + G_T128 + (uint32_t)(warp_m * 64) * G_ROWB;
    const uint32_t bB  = s + NA * G_T128 + (uint32_t)(warp_n * 64) * G_ROWB;
#pragma unroll
    for (int ks = 0; ks < 4; ks++) {
        uint32_t ah[4][4], al[4][4], bb[4][4];
#pragma unroll
        for (int mt = 0; mt < 4; mt++) {
            ldsm4(ah[mt], aB0 + (uint32_t)(mt * 16) * G_ROWB + ks * 32 + a_off);
            if (NA == 2)
                ldsm4(al[mt], aB1 + (uint32_t)(mt * 16) * G_ROWB + ks * 32 + a_off);
        }
#pragma unroll
        for (int p = 0; p < 4; p++)
            ldsm4(bb[p], bB + (uint32_t)(p * 16) * G_ROWB + ks * 32 + b_off);
#pragma unroll
        for (int mt = 0; mt < 4; mt++)
#pragma unroll
            for (int nt = 0; nt < 8; nt++) {
                float* c = acc[mt][nt];
                const uint32_t* bp = &bb[nt >> 1][(nt & 1) * 2];
                mma_f16(c, ah[mt], bp);
                if (NA == 2) mma_f16(c, al[mt], bp);
            }
    }
}

// ---- fused QKV projection ----
struct ProjOne {
    const __half *A, *W;
    const float* bias;
    __half *O;
    float scale;
};
struct Proj3Args { ProjOne p[3]; };

__global__ __launch_bounds__(128, 2)
void proj3_kernel(Proj3Args args)
{
    extern __shared__ __align__(128) char smem[];
    const ProjOne P = args.p[blockIdx.z];
    const uint32_t sb = smem_u32(smem);
    const int tid = threadIdx.x, lane = tid & 31, wid = tid >> 5;
    const int row0 = blockIdx.y * 128, col0 = blockIdx.x * 128;
    const int warp_m = wid >> 1, warp_n = wid & 1;
    const int la = lane & 7, lb8 = (lane >> 3) & 1, lb16 = lane >> 4;
    const uint32_t a_off = (uint32_t)((la + lb8 * 8) * G_ROWB + lb16 * 16);
    const uint32_t b_off = (uint32_t)((la + lb16 * 8) * G_ROWB + lb8 * 16);

    const __half* srcA = P.A + (size_t)row0 * 1024;
    const __half* srcB = P.W + (size_t)col0 * 1024;

    float acc[4][8][4];
#pragma unroll
    for (int a = 0; a < 4; a++)
#pragma unroll
        for (int b = 0; b < 8; b++)
#pragma unroll
            for (int c = 0; c < 4; c++) acc[a][b][c] = 0.f;

    gemm_load_stage<1>(sb, tid, srcA, nullptr, srcB, 0, 0);   CP_COMMIT();
    gemm_load_stage<1>(sb, tid, srcA, nullptr, srcB, 1, 64);  CP_COMMIT();
    for (int c = 0; c < 16; c++) {
        CP_WAIT1();
        __syncthreads();
        gemm_compute_stage<1>(sb, warp_m, warp_n, a_off, b_off, c % 3, acc);
        if (c + 2 < 16)
            gemm_load_stage<1>(sb, tid, srcA, nullptr, srcB, (c + 2) % 3, (c + 2) * 64);
        CP_COMMIT();
    }

    const int r_base = row0 + warp_m * 64, c_base = col0 + warp_n * 64;
#pragma unroll
    for (int mt = 0; mt < 4; mt++) {
        const int r = r_base + mt * 16 + (lane >> 2);
#pragma unroll
        for (int nt = 0; nt < 8; nt++) {
            const int cc = c_base + nt * 8 + (lane & 3) * 2;
            const float b0 = __ldg(P.bias + cc), b1 = __ldg(P.bias + cc + 1);
            *(__half2*)(P.O + (size_t)r * 1024 + cc) =
                __floats2half2_rn((acc[mt][nt][0] + b0) * P.scale,
                                  (acc[mt][nt][1] + b1) * P.scale);
            *(__half2*)(P.O + (size_t)(r + 8) * 1024 + cc) =
                __floats2half2_rn((acc[mt][nt][2] + b0) * P.scale,
                                  (acc[mt][nt][3] + b1) * P.scale);
        }
    }
}

// ---- output projection: C 2-term x W 1-term, fp32 out. 2-stage pipeline. ----
__global__ __launch_bounds__(128, 2)
void gemmF_kernel(const __half* __restrict__ Ch, const __half* __restrict__ Cl,
                  const __half* __restrict__ W,
                  const float* __restrict__ bias, float* __restrict__ C)
{
    extern __shared__ __align__(128) char smem[];
    const uint32_t sb = smem_u32(smem);
    const int tid = threadIdx.x, lane = tid & 31, wid = tid >> 5;
    const int row0 = blockIdx.y * 128, col0 = blockIdx.x * 128;
    const int warp_m = wid >> 1, warp_n = wid & 1;
    const int la = lane & 7, lb8 = (lane >> 3) & 1, lb16 = lane >> 4;
    const uint32_t a_off = (uint32_t)((la + lb8 * 8) * G_ROWB + lb16 * 16);
    const uint32_t b_off = (uint32_t)((la + lb16 * 8) * G_ROWB + lb8 * 16);

    const __half* srcA0 = Ch + (size_t)row0 * 1024;
    const __half* srcA1 = Cl + (size_t)row0 * 1024;
    const __half* srcB  = W  + (size_t)col0 * 1024;

    float acc[4][8][4];
#pragma unroll
    for (int a = 0; a < 4; a++)
#pragma unroll
        for (int b = 0; b < 8; b++)
#pragma unroll
            for (int c = 0; c < 4; c++) acc[a][b][c] = 0.f;

    gemm_load_stage<2>(sb, tid, srcA0, srcA1, srcB, 0, 0);   CP_COMMIT();
    for (int c = 0; c < 16; c++) {
        CP_WAIT0();
        __syncthreads();
        if (c + 1 < 16) {
            gemm_load_stage<2>(sb, tid, srcA0, srcA1, srcB, (c + 1) & 1, (c + 1) * 64);
            CP_COMMIT();
        }
        gemm_compute_stage<2>(sb, warp_m, warp_n, a_off, b_off, c & 1, acc);
        __syncthreads();
    }

    const int r_base = row0 + warp_m * 64, c_base = col0 + warp_n * 64;
#pragma unroll
    for (int mt = 0; mt < 4; mt++) {
        const int r = r_base + mt * 16 + (lane >> 2);
#pragma unroll
        for (int nt = 0; nt < 8; nt++) {
            const int cc = c_base + nt * 8 + (lane & 3) * 2;
            const float b0 = __ldg(bias + cc), b1 = __ldg(bias + cc + 1);
            float2 o0, o1;
            o0.x = acc[mt][nt][0] + b0; o0.y = acc[mt][nt][1] + b1;
            o1.x = acc[mt][nt][2] + b0; o1.y = acc[mt][nt][3] + b1;
            *(float2*)(C + (size_t)r * 1024 + cc)       = o0;
            *(float2*)(C + (size_t)(r + 8) * 1024 + cc) = o1;
        }
    }
}

// =================================================================================
// Flash attention (R13 shape): 4 warps / 128 thr, warp m-tile 32, 128 q-rows/tile,
// kv 64/iter, 3-stage ring — PERSISTENT: 296 CTAs loop over all 1024 tiles.
// =================================================================================
#define A_STRIDE_B 144
#define A_TILE_B   (64 * A_STRIDE_B)    // 9216
#define A_STAGE_B  (2 * A_TILE_B)       // 18432 (K|Vt)
#define A_SMEM_TOT (6 * A_TILE_B)       // 55296
#define A_NTILES   ((SEQ / 128) * BATCH * NHEAD)   // 1024

__global__ __launch_bounds__(128, 2)
void attention_mma_kernel(const __half* __restrict__ Q16,
                          const __half* __restrict__ K16, const __half* __restrict__ VT,
                          __half* __restrict__ CH, __half* __restrict__ CL)
{
    extern __shared__ __align__(128) char smem[];
    const uint32_t sb = smem_u32(smem);
    const int tid  = threadIdx.x;
    const int lane = tid & 31, wid = tid >> 5;   // wid 0..3

    const int la   = lane & 7;
    const int lb8  = (lane >> 3) & 1;
    const int lb16 = lane >> 4;
    const uint32_t a_off = (uint32_t)((la + lb8 * 8) * A_STRIDE_B + lb16 * 16);
    const uint32_t b_off = (uint32_t)((la + lb16 * 8) * A_STRIDE_B + lb8 * 16);

    for (int tile = blockIdx.x; tile < A_NTILES; tile += gridDim.x) {
        // qi-fastest order: consecutive tiles share bh -> K/V L2 reuse
        const int bh = tile >> 4;              // / (SEQ/128)
        const int qi = tile & 15;
        const int b = bh >> 4, h = bh & 15;
        const int q0 = qi * 128;

        // ---- stage Q (128 rows) and move to registers ----
#pragma unroll
        for (int i = 0; i < 8; i++) {
            int c = tid + i * 128;
            int r = c >> 3, ch = c & 7;
            const size_t g = (size_t)(b * SEQ + q0 + r) * D_MODEL + h * 64 + ch * 8;
            CP_ASYNC16(sb + r * A_STRIDE_B + ch * 16, (const void*)(Q16 + g));
        }
        CP_COMMIT();
        CP_WAIT0();
        __syncthreads();

        uint32_t qh[4][2][4];
#pragma unroll
        for (int ks = 0; ks < 4; ks++)
#pragma unroll
            for (int mt = 0; mt < 2; mt++)
                ldsm4(qh[ks][mt],
                      sb + (uint32_t)((wid * 32 + mt * 16)) * A_STRIDE_B + ks * 32 + a_off);
        __syncthreads();

        // ---- KV loader ----
        auto load_stage = [&](int st, int kv0) {
#pragma unroll
            for (int i = 0; i < 8; i++) {
                const int c = tid + i * 128;
                const int row = c >> 3, ch = c & 7;
                const __half* g;
                uint32_t soff;
                if (row < 64) {
                    g = K16 + (size_t)(b * SEQ + kv0 + row) * D_MODEL + h * 64;
                    soff = (uint32_t)row * A_STRIDE_B;
                } else {
                    g = VT + (size_t)(bh * 64 + (row - 64)) * SEQ + kv0;
                    soff = A_TILE_B + (uint32_t)(row - 64) * A_STRIDE_B;
                }
                CP_ASYNC16(sb + st * A_STAGE_B + soff + ch * 16, (const void*)(g + ch * 8));
            }
        };

        load_stage(0, 0);  CP_COMMIT();
        load_stage(1, 64); CP_COMMIT();

        float o[2][8][4];
#pragma unroll
        for (int mt = 0; mt < 2; mt++)
#pragma unroll
            for (int t = 0; t < 8; t++)
#pragma unroll
                for (int j = 0; j < 4; j++) o[mt][t][j] = 0.f;
        float m_r[4] = {-1e30f, -1e30f, -1e30f, -1e30f};
        float l_r[4] = {0.f, 0.f, 0.f, 0.f};

        for (int it = 0; it < 32; it++) {
            CP_WAIT1();
            __syncthreads();
            const uint32_t st = sb + (it % 3) * A_STAGE_B;

            // ---- S = Q K^T ----
            float s[2][8][4];
#pragma unroll
            for (int mt = 0; mt < 2; mt++)
#pragma unroll
                for (int t = 0; t < 8; t++)
#pragma unroll
                    for (int j = 0; j < 4; j++) s[mt][t][j] = 0.f;
#pragma unroll
            for (int ks = 0; ks < 4; ks++) {
#pragma unroll
                for (int np = 0; np < 4; np++) {
                    uint32_t k4[4];
                    const uint32_t base = (uint32_t)(np * 16) * A_STRIDE_B + ks * 32 + b_off;
                    ldsm4(k4, st + base);
#pragma unroll
                    for (int mt = 0; mt < 2; mt++) {
                        mma_f16(s[mt][2 * np],     qh[ks][mt], k4);
                        mma_f16(s[mt][2 * np + 1], qh[ks][mt], k4 + 2);
                    }
                }
            }

            // ---- online softmax ----
#pragma unroll
            for (int mt = 0; mt < 2; mt++)
#pragma unroll
                for (int r = 0; r < 2; r++) {
                    const int ri = mt * 2 + r;
                    float mx = s[mt][0][2 * r];
#pragma unroll
                    for (int t = 0; t < 8; t++) {
                        mx = fmaxf(mx, s[mt][t][2 * r]);
                        mx = fmaxf(mx, s[mt][t][2 * r + 1]);
                    }
                    mx = fmaxf(mx, __shfl_xor_sync(0xffffffffu, mx, 1));
                    mx = fmaxf(mx, __shfl_xor_sync(0xffffffffu, mx, 2));
                    float mn = fmaxf(m_r[ri], mx);
                    float al = __expf(m_r[ri] - mn);
                    m_r[ri] = mn;
                    float sum = 0.f;
#pragma unroll
                    for (int t = 0; t < 8; t++) {
                        float p0 = __expf(s[mt][t][2 * r]     - mn);
                        float p1 = __expf(s[mt][t][2 * r + 1] - mn);
                        s[mt][t][2 * r] = p0; s[mt][t][2 * r + 1] = p1;
                        sum += p0 + p1;
                    }
                    sum += __shfl_xor_sync(0xffffffffu, sum, 1);
                    sum += __shfl_xor_sync(0xffffffffu, sum, 2);
                    l_r[ri] = l_r[ri] * al + sum;
#pragma unroll
                    for (int t = 0; t < 8; t++) {
                        o[mt][t][2 * r] *= al; o[mt][t][2 * r + 1] *= al;
                    }
                }

            // ---- O += P V ----
#pragma unroll
            for (int ks = 0; ks < 4; ks++) {
                const int t0 = 2 * ks, t1 = 2 * ks + 1;
                uint32_t pa[2][4];
#pragma unroll
                for (int mt = 0; mt < 2; mt++) {
                    pa[mt][0] = pack_h(s[mt][t0][0], s[mt][t0][1]);
                    pa[mt][1] = pack_h(s[mt][t0][2], s[mt][t0][3]);
                    pa[mt][2] = pack_h(s[mt][t1][0], s[mt][t1][1]);
                    pa[mt][3] = pack_h(s[mt][t1][2], s[mt][t1][3]);
                }
#pragma unroll
                for (int np = 0; np < 4; np++) {
                    uint32_t v4[4];
                    const uint32_t base = (uint32_t)(np * 16) * A_STRIDE_B + ks * 32 + b_off;
                    ldsm4(v4, st + A_TILE_B + base);
#pragma unroll
                    for (int mt = 0; mt < 2; mt++) {
                        mma_f16(o[mt][2 * np],     pa[mt], v4);
                        mma_f16(o[mt][2 * np + 1], pa[mt], v4 + 2);
                    }
                }
            }

            if (it + 2 < 32) load_stage((it + 2) % 3, (it + 2) * 64);
            CP_COMMIT();
        }

        // ---- epilogue: context hi/lo ----
#pragma unroll
        for (int mt = 0; mt < 2; mt++) {
            const float inv0 = 1.f / l_r[mt * 2];
            const float inv1 = 1.f / l_r[mt * 2 + 1];
            const int row0 = q0 + wid * 32 + mt * 16 + (lane >> 2);
#pragma unroll
            for (int t = 0; t < 8; t++) {
                const int col = h * 64 + t * 8 + (lane & 3) * 2;
                store_hilo(CH, CL, (size_t)(b * SEQ + row0) * D_MODEL + col,
                           o[mt][t][0] * inv0, o[mt][t][1] * inv0);
                store_hilo(CH, CL, (size_t)(b * SEQ + row0 + 8) * D_MODEL + col,
                           o[mt][t][2] * inv1, o[mt][t][3] * inv1);
            }
        }

        // drain trailing cp.async groups before reusing smem for next tile's Q
        CP_WAIT0();
        __syncthreads();
    }
}

// =================================================================================
// launch
// =================================================================================
extern "C" void kernel_launch(void* const* d_in, const int* in_sizes, int n_in,
                              void* d_out, int out_size)
{
    const float* x_q = (const float*)d_in[0];
    const float* x_k = (const float*)d_in[1];
    const float* x_v = (const float*)d_in[2];
    const float* wq  = (const float*)d_in[3];
    const float* bq  = (const float*)d_in[4];
    const float* wk  = (const float*)d_in[5];
    const float* bk  = (const float*)d_in[6];
    const float* wv  = (const float*)d_in[7];
    const float* bv  = (const float*)d_in[8];
    const float* wo  = (const float*)d_in[9];
    const float* bo  = (const float*)d_in[10];
    float* out = (float*)d_out;

    __half *x0, *x1, *x2, *q16, *k16, *v16, *vt, *ch, *cl;
    __half *w0, *w1, *w2, *w3;
    cudaGetSymbolAddress((void**)&x0,  g_X0);
    cudaGetSymbolAddress((void**)&x1,  g_X1);
    cudaGetSymbolAddress((void**)&x2,  g_X2);
    cudaGetSymbolAddress((void**)&q16, g_Q16);
    cudaGetSymbolAddress((void**)&k16, g_K16);
    cudaGetSymbolAddress((void**)&v16, g_V16);
    cudaGetSymbolAddress((void**)&vt,  g_VT);
    cudaGetSymbolAddress((void**)&ch,  g_CH);
    cudaGetSymbolAddress((void**)&cl,  g_CL);
    cudaGetSymbolAddress((void**)&w0,  g_W0);
    cudaGetSymbolAddress((void**)&w1,  g_W1);
    cudaGetSymbolAddress((void**)&w2,  g_W2);
    cudaGetSymbolAddress((void**)&w3,  g_W3);

    static int attr_set = 0;
    const int proj_smem = 3 * 2 * G_T128;   // 110592
    const int gemf_smem = 2 * 3 * G_T128;   // 110592
    if (!attr_set) {
        cudaFuncSetAttribute(proj3_kernel,
                             cudaFuncAttributeMaxDynamicSharedMemorySize, proj_smem);
        cudaFuncSetAttribute(gemmF_kernel,
                             cudaFuncAttributeMaxDynamicSharedMemorySize, gemf_smem);
        cudaFuncSetAttribute(attention_mma_kernel,
                             cudaFuncAttributeMaxDynamicSharedMemorySize, A_SMEM_TOT);
        attr_set = 1;
    }

    const int NX = M_TOT * D_MODEL;
    const int NW = D_MODEL * D_MODEL;
    dim3 cb(256);

    // converts
    {
        Conv3Args cx; cx.src[0] = x_q; cx.src[1] = x_k; cx.src[2] = x_v;
        cx.dst[0] = x0; cx.dst[1] = x1; cx.dst[2] = x2;
        conv3_kernel<<<dim3((NX / 4 + 255) / 256, 1, 3), cb>>>(cx, NX);
        Conv3Args cw; cw.src[0] = wq; cw.src[1] = wk; cw.src[2] = wv;
        cw.dst[0] = w0; cw.dst[1] = w1; cw.dst[2] = w2;
        conv3_kernel<<<dim3((NW / 4 + 255) / 256, 1, 3), cb>>>(cw, NW);
        conv1_kernel<<<(NW / 4 + 255) / 256, cb>>>(wo, w3, NW);
    }

    // fused QKV projections (fp16 1-term; Q pre-scaled)
    Proj3Args pa;
    pa.p[0] = { x0, w0, bq, q16, 0.125f };
    pa.p[1] = { x1, w1, bk, k16, 1.0f };
    pa.p[2] = { x2, w2, bv, v16, 1.0f };
    proj3_kernel<<<dim3(8, 64, 3), 128, proj_smem>>>(pa);

    // V transpose
    vtrans_kernel<<<dim3(SEQ / 32, 2, BATCH * NHEAD), 256>>>(v16, vt);

    // attention — persistent: 296 CTAs (2/SM x 148) loop over 1024 tiles
    attention_mma_kernel<<<296, 128, A_SMEM_TOT>>>(q16, k16, vt, ch, cl);

    // output projection (C hi/lo x W, 2 products)
    gemmF_kernel<<<dim3(8, 64), 128, gemf_smem>>>(ch, cl, w3, bo, out);
}

// round 17
// speedup vs baseline: 1.0621x; 1.0366x over previous
#include <cuda_runtime.h>
#include <cuda_fp16.h>
#include <math.h>
#include <cstdint>

#define D_MODEL 1024
#define NHEAD   16
#define D_K     64
#define BATCH   4
#define SEQ     2048
#define M_TOT   (BATCH * SEQ)   // 8192

// ---------------- scratch (device globals: allocation-free rule) ----------------
__device__ __half g_X0 [M_TOT * D_MODEL];
__device__ __half g_X1 [M_TOT * D_MODEL];
__device__ __half g_X2 [M_TOT * D_MODEL];
__device__ __half g_Q16[M_TOT * D_MODEL];
__device__ __half g_K16[M_TOT * D_MODEL];
__device__ __half g_V16[M_TOT * D_MODEL];
__device__ __half g_CH [M_TOT * D_MODEL];
__device__ __half g_CL [M_TOT * D_MODEL];
__device__ __half g_W0 [D_MODEL * D_MODEL];
__device__ __half g_W1 [D_MODEL * D_MODEL];
__device__ __half g_W2 [D_MODEL * D_MODEL];
__device__ __half g_W3 [D_MODEL * D_MODEL];

// ====================== helpers ======================
__device__ __forceinline__ uint32_t smem_u32(const void* p) {
    uint32_t a;
    asm("{ .reg .u64 t; cvta.to.shared.u64 t, %1; cvt.u32.u64 %0, t; }" : "=r"(a) : "l"(p));
    return a;
}
__device__ __forceinline__ void ldsm4(uint32_t* r, uint32_t addr) {
    asm volatile("ldmatrix.sync.aligned.m8n8.x4.shared.b16 {%0,%1,%2,%3}, [%4];"
        : "=r"(r[0]), "=r"(r[1]), "=r"(r[2]), "=r"(r[3]) : "r"(addr));
}
__device__ __forceinline__ void ldsm4t(uint32_t* r, uint32_t addr) {
    asm volatile("ldmatrix.sync.aligned.m8n8.x4.trans.shared.b16 {%0,%1,%2,%3}, [%4];"
        : "=r"(r[0]), "=r"(r[1]), "=r"(r[2]), "=r"(r[3]) : "r"(addr));
}
__device__ __forceinline__ void mma_f16(float* c, const uint32_t* a, const uint32_t* b) {
    asm volatile("mma.sync.aligned.m16n8k16.row.col.f32.f16.f16.f32 "
        "{%0,%1,%2,%3}, {%4,%5,%6,%7}, {%8,%9}, {%0,%1,%2,%3};"
        : "+f"(c[0]), "+f"(c[1]), "+f"(c[2]), "+f"(c[3])
        : "r"(a[0]), "r"(a[1]), "r"(a[2]), "r"(a[3]), "r"(b[0]), "r"(b[1]));
}
__device__ __forceinline__ uint32_t pack_h(float x, float y) {
    __half2 h = __floats2half2_rn(x, y);
    return *(uint32_t*)&h;
}
__device__ __forceinline__ void store_hilo(__half* H, __half* L, size_t off, float x, float y) {
    __half hx = __float2half_rn(x), hy = __float2half_rn(y);
    __half lx = __float2half_rn(x - __half2float(hx));
    __half ly = __float2half_rn(y - __half2float(hy));
    *(__half2*)(H + off) = __halves2half2(hx, hy);
    *(__half2*)(L + off) = __halves2half2(lx, ly);
}
#define CP_ASYNC16(s, g) asm volatile("cp.async.cg.shared.global [%0], [%1], 16;" :: "r"(s), "l"(g) : "memory")
#define CP_COMMIT()      asm volatile("cp.async.commit_group;" ::: "memory")
#define CP_WAIT1()       asm volatile("cp.async.wait_group 1;" ::: "memory")
#define CP_WAIT0()       asm volatile("cp.async.wait_group 0;" ::: "memory")

// =================================================================================
// converts (4-way batched)
// =================================================================================
struct ConvNArgs { const float* src[4]; __half* dst[4]; };

__global__ void convN_kernel(ConvNArgs a, int n)
{
    const float* x = a.src[blockIdx.z];
    __half* o = a.dst[blockIdx.z];
    int idx = (blockIdx.x * blockDim.x + threadIdx.x) * 4;
    if (idx >= n) return;
    float4 v = *(const float4*)(x + idx);
    *(__half2*)(o + idx)     = __floats2half2_rn(v.x, v.y);
    *(__half2*)(o + idx + 2) = __floats2half2_rn(v.z, v.w);
}

// =================================================================================
// 4-warp GEMM core: CTA 128x128, BK=64, warp tile 64x64 (warp grid 2x2). 2 CTAs/SM.
// =================================================================================
#define G_ROWB   144
#define G_T128   (128 * G_ROWB)         // 18432

template<int NA>
__device__ __forceinline__ void gemm_load_stage(
    uint32_t sb, int tid,
    const __half* srcA0, const __half* srcA1, const __half* srcB,
    int st, int k0)
{
    constexpr int STAGE_B = (NA + 1) * G_T128;
    constexpr int NCH = (NA * 128 + 128) * 8;
#pragma unroll
    for (int i = 0; i < NCH / 128; i++) {
        const int c = tid + i * 128;
        const int row = c >> 3, ch = c & 7;
        const __half* g;
        uint32_t soff;
        if (row < 128) {
            g = srcA0 + (size_t)row * 1024;
            soff = (uint32_t)row * G_ROWB;
        } else if (NA == 2 && row < 256) {
            g = srcA1 + (size_t)(row - 128) * 1024;
            soff = G_T128 + (uint32_t)(row - 128) * G_ROWB;
        } else {
            const int br = row - NA * 128;
            g = srcB + (size_t)br * 1024;
            soff = NA * G_T128 + (uint32_t)br * G_ROWB;
        }
        CP_ASYNC16(sb + st * STAGE_B + soff + ch * 16, (const void*)(g + k0 + ch * 8));
    }
}

template<int NA>
__device__ __forceinline__ void gemm_compute_stage(
    uint32_t sb, int warp_m, int warp_n, uint32_t a_off, uint32_t b_off,
    int st, float acc[4][8][4])
{
    constexpr int STAGE_B = (NA + 1) * G_T128;
    const uint32_t s   = sb + st * STAGE_B;
    const uint32_t aB0 = s + (uint32_t)(warp_m * 64) * G_ROWB;
    const uint32_t aB1 = s + G_T128 + (uint32_t)(warp_m * 64) * G_ROWB;
    const uint32_t bB  = s + NA * G_T128 + (uint32_t)(warp_n * 64) * G_ROWB;
#pragma unroll
    for (int ks = 0; ks < 4; ks++) {
        uint32_t ah[4][4], al[4][4], bb[4][4];
#pragma unroll
        for (int mt = 0; mt < 4; mt++) {
            ldsm4(ah[mt], aB0 + (uint32_t)(mt * 16) * G_ROWB + ks * 32 + a_off);
            if (NA == 2)
                ldsm4(al[mt], aB1 + (uint32_t)(mt * 16) * G_ROWB + ks * 32 + a_off);
        }
#pragma unroll
        for (int p = 0; p < 4; p++)
            ldsm4(bb[p], bB + (uint32_t)(p * 16) * G_ROWB + ks * 32 + b_off);
#pragma unroll
        for (int mt = 0; mt < 4; mt++)
#pragma unroll
            for (int nt = 0; nt < 8; nt++) {
                float* c = acc[mt][nt];
                const uint32_t* bp = &bb[nt >> 1][(nt & 1) * 2];
                mma_f16(c, ah[mt], bp);
                if (NA == 2) mma_f16(c, al[mt], bp);
            }
    }
}

// ---- fused QKV projection ----
struct ProjOne {
    const __half *A, *W;
    const float* bias;
    __half *O;
    float scale;
};
struct Proj3Args { ProjOne p[3]; };

__global__ __launch_bounds__(128, 2)
void proj3_kernel(Proj3Args args)
{
    extern __shared__ __align__(128) char smem[];
    const ProjOne P = args.p[blockIdx.z];
    const uint32_t sb = smem_u32(smem);
    const int tid = threadIdx.x, lane = tid & 31, wid = tid >> 5;
    const int row0 = blockIdx.y * 128, col0 = blockIdx.x * 128;
    const int warp_m = wid >> 1, warp_n = wid & 1;
    const int la = lane & 7, lb8 = (lane >> 3) & 1, lb16 = lane >> 4;
    const uint32_t a_off = (uint32_t)((la + lb8 * 8) * G_ROWB + lb16 * 16);
    const uint32_t b_off = (uint32_t)((la + lb16 * 8) * G_ROWB + lb8 * 16);

    const __half* srcA = P.A + (size_t)row0 * 1024;
    const __half* srcB = P.W + (size_t)col0 * 1024;

    float acc[4][8][4];
#pragma unroll
    for (int a = 0; a < 4; a++)
#pragma unroll
        for (int b = 0; b < 8; b++)
#pragma unroll
            for (int c = 0; c < 4; c++) acc[a][b][c] = 0.f;

    gemm_load_stage<1>(sb, tid, srcA, nullptr, srcB, 0, 0);   CP_COMMIT();
    gemm_load_stage<1>(sb, tid, srcA, nullptr, srcB, 1, 64);  CP_COMMIT();
    for (int c = 0; c < 16; c++) {
        CP_WAIT1();
        __syncthreads();
        gemm_compute_stage<1>(sb, warp_m, warp_n, a_off, b_off, c % 3, acc);
        if (c + 2 < 16)
            gemm_load_stage<1>(sb, tid, srcA, nullptr, srcB, (c + 2) % 3, (c + 2) * 64);
        CP_COMMIT();
    }

    const int r_base = row0 + warp_m * 64, c_base = col0 + warp_n * 64;
#pragma unroll
    for (int mt = 0; mt < 4; mt++) {
        const int r = r_base + mt * 16 + (lane >> 2);
#pragma unroll
        for (int nt = 0; nt < 8; nt++) {
            const int cc = c_base + nt * 8 + (lane & 3) * 2;
            const float b0 = __ldg(P.bias + cc), b1 = __ldg(P.bias + cc + 1);
            *(__half2*)(P.O + (size_t)r * 1024 + cc) =
                __floats2half2_rn((acc[mt][nt][0] + b0) * P.scale,
                                  (acc[mt][nt][1] + b1) * P.scale);
            *(__half2*)(P.O + (size_t)(r + 8) * 1024 + cc) =
                __floats2half2_rn((acc[mt][nt][2] + b0) * P.scale,
                                  (acc[mt][nt][3] + b1) * P.scale);
        }
    }
}

// ---- output projection: C 2-term x W 1-term, fp32 out. 2-stage pipeline. ----
__global__ __launch_bounds__(128, 2)
void gemmF_kernel(const __half* __restrict__ Ch, const __half* __restrict__ Cl,
                  const __half* __restrict__ W,
                  const float* __restrict__ bias, float* __restrict__ C)
{
    extern __shared__ __align__(128) char smem[];
    const uint32_t sb = smem_u32(smem);
    const int tid = threadIdx.x, lane = tid & 31, wid = tid >> 5;
    const int row0 = blockIdx.y * 128, col0 = blockIdx.x * 128;
    const int warp_m = wid >> 1, warp_n = wid & 1;
    const int la = lane & 7, lb8 = (lane >> 3) & 1, lb16 = lane >> 4;
    const uint32_t a_off = (uint32_t)((la + lb8 * 8) * G_ROWB + lb16 * 16);
    const uint32_t b_off = (uint32_t)((la + lb16 * 8) * G_ROWB + lb8 * 16);

    const __half* srcA0 = Ch + (size_t)row0 * 1024;
    const __half* srcA1 = Cl + (size_t)row0 * 1024;
    const __half* srcB  = W  + (size_t)col0 * 1024;

    float acc[4][8][4];
#pragma unroll
    for (int a = 0; a < 4; a++)
#pragma unroll
        for (int b = 0; b < 8; b++)
#pragma unroll
            for (int c = 0; c < 4; c++) acc[a][b][c] = 0.f;

    gemm_load_stage<2>(sb, tid, srcA0, srcA1, srcB, 0, 0);   CP_COMMIT();
    for (int c = 0; c < 16; c++) {
        CP_WAIT0();
        __syncthreads();
        if (c + 1 < 16) {
            gemm_load_stage<2>(sb, tid, srcA0, srcA1, srcB, (c + 1) & 1, (c + 1) * 64);
            CP_COMMIT();
        }
        gemm_compute_stage<2>(sb, warp_m, warp_n, a_off, b_off, c & 1, acc);
        __syncthreads();
    }

    const int r_base = row0 + warp_m * 64, c_base = col0 + warp_n * 64;
#pragma unroll
    for (int mt = 0; mt < 4; mt++) {
        const int r = r_base + mt * 16 + (lane >> 2);
#pragma unroll
        for (int nt = 0; nt < 8; nt++) {
            const int cc = c_base + nt * 8 + (lane & 3) * 2;
            const float b0 = __ldg(bias + cc), b1 = __ldg(bias + cc + 1);
            float2 o0, o1;
            o0.x = acc[mt][nt][0] + b0; o0.y = acc[mt][nt][1] + b1;
            o1.x = acc[mt][nt][2] + b0; o1.y = acc[mt][nt][3] + b1;
            *(float2*)(C + (size_t)r * 1024 + cc)       = o0;
            *(float2*)(C + (size_t)(r + 8) * 1024 + cc) = o1;
        }
    }
}

// =================================================================================
// Flash attention (R13 shape): 4 warps / 128 thr, warp m-tile 32, 128 q-rows/CTA,
// kv 64/iter, 3-stage ring. V staged ROW-MAJOR [kv][d] and consumed via
// ldmatrix.trans — no V-transpose kernel / buffer needed.
// =================================================================================
#define A_STRIDE_B 144
#define A_TILE_B   (64 * A_STRIDE_B)    // 9216
#define A_STAGE_B  (2 * A_TILE_B)       // 18432 (K|V)
#define A_SMEM_TOT (6 * A_TILE_B)       // 55296

__global__ __launch_bounds__(128, 2)
void attention_mma_kernel(const __half* __restrict__ Q16,
                          const __half* __restrict__ K16, const __half* __restrict__ V16,
                          __half* __restrict__ CH, __half* __restrict__ CL)
{
    extern __shared__ __align__(128) char smem[];
    const uint32_t sb = smem_u32(smem);
    const int tid  = threadIdx.x;
    const int lane = tid & 31, wid = tid >> 5;   // wid 0..3
    const int bh = blockIdx.y;
    const int b = bh >> 4, h = bh & 15;
    const int q0 = blockIdx.x * 128;

    const int la   = lane & 7;
    const int lb8  = (lane >> 3) & 1;
    const int lb16 = lane >> 4;
    const uint32_t a_off = (uint32_t)((la + lb8 * 8) * A_STRIDE_B + lb16 * 16);
    const uint32_t b_off = (uint32_t)((la + lb16 * 8) * A_STRIDE_B + lb8 * 16);
    // trans-ldsm lane offset for V (rows = kv): identical form to a_off
    const uint32_t v_off = a_off;

    // ---- stage Q (128 rows) and move to registers ----
    {
#pragma unroll
        for (int i = 0; i < 8; i++) {
            int c = tid + i * 128;
            int r = c >> 3, ch = c & 7;
            const size_t g = (size_t)(b * SEQ + q0 + r) * D_MODEL + h * 64 + ch * 8;
            CP_ASYNC16(sb + r * A_STRIDE_B + ch * 16, (const void*)(Q16 + g));
        }
        CP_COMMIT();
        CP_WAIT0();
        __syncthreads();
    }
    uint32_t qh[4][2][4];
#pragma unroll
    for (int ks = 0; ks < 4; ks++)
#pragma unroll
        for (int mt = 0; mt < 2; mt++)
            ldsm4(qh[ks][mt],
                  sb + (uint32_t)((wid * 32 + mt * 16)) * A_STRIDE_B + ks * 32 + a_off);
    __syncthreads();

    // ---- KV loader: both K and V row-major [kv][d], identical addressing ----
    auto load_stage = [&](int st, int kv0) {
#pragma unroll
        for (int i = 0; i < 8; i++) {
            const int c = tid + i * 128;
            const int row = c >> 3, ch = c & 7;
            const __half* g;
            uint32_t soff;
            if (row < 64) {
                g = K16 + (size_t)(b * SEQ + kv0 + row) * D_MODEL + h * 64;
                soff = (uint32_t)row * A_STRIDE_B;
            } else {
                g = V16 + (size_t)(b * SEQ + kv0 + (row - 64)) * D_MODEL + h * 64;
                soff = A_TILE_B + (uint32_t)(row - 64) * A_STRIDE_B;
            }
            CP_ASYNC16(sb + st * A_STAGE_B + soff + ch * 16, (const void*)(g + ch * 8));
        }
    };

    load_stage(0, 0);  CP_COMMIT();
    load_stage(1, 64); CP_COMMIT();

    float o[2][8][4];
#pragma unroll
    for (int mt = 0; mt < 2; mt++)
#pragma unroll
        for (int t = 0; t < 8; t++)
#pragma unroll
            for (int j = 0; j < 4; j++) o[mt][t][j] = 0.f;
    float m_r[4] = {-1e30f, -1e30f, -1e30f, -1e30f};
    float l_r[4] = {0.f, 0.f, 0.f, 0.f};

    for (int it = 0; it < 32; it++) {
        CP_WAIT1();
        __syncthreads();
        const uint32_t st = sb + (it % 3) * A_STAGE_B;

        // ---- S = Q K^T ----
        float s[2][8][4];
#pragma unroll
        for (int mt = 0; mt < 2; mt++)
#pragma unroll
            for (int t = 0; t < 8; t++)
#pragma unroll
                for (int j = 0; j < 4; j++) s[mt][t][j] = 0.f;
#pragma unroll
        for (int ks = 0; ks < 4; ks++) {
#pragma unroll
            for (int np = 0; np < 4; np++) {
                uint32_t k4[4];
                const uint32_t base = (uint32_t)(np * 16) * A_STRIDE_B + ks * 32 + b_off;
                ldsm4(k4, st + base);
#pragma unroll
                for (int mt = 0; mt < 2; mt++) {
                    mma_f16(s[mt][2 * np],     qh[ks][mt], k4);
                    mma_f16(s[mt][2 * np + 1], qh[ks][mt], k4 + 2);
                }
            }
        }

        // ---- online softmax ----
#pragma unroll
        for (int mt = 0; mt < 2; mt++)
#pragma unroll
            for (int r = 0; r < 2; r++) {
                const int ri = mt * 2 + r;
                float mx = s[mt][0][2 * r];
#pragma unroll
                for (int t = 0; t < 8; t++) {
                    mx = fmaxf(mx, s[mt][t][2 * r]);
                    mx = fmaxf(mx, s[mt][t][2 * r + 1]);
                }
                mx = fmaxf(mx, __shfl_xor_sync(0xffffffffu, mx, 1));
                mx = fmaxf(mx, __shfl_xor_sync(0xffffffffu, mx, 2));
                float mn = fmaxf(m_r[ri], mx);
                float al = __expf(m_r[ri] - mn);
                m_r[ri] = mn;
                float sum = 0.f;
#pragma unroll
                for (int t = 0; t < 8; t++) {
                    float p0 = __expf(s[mt][t][2 * r]     - mn);
                    float p1 = __expf(s[mt][t][2 * r + 1] - mn);
                    s[mt][t][2 * r] = p0; s[mt][t][2 * r + 1] = p1;
                    sum += p0 + p1;
                }
                sum += __shfl_xor_sync(0xffffffffu, sum, 1);
                sum += __shfl_xor_sync(0xffffffffu, sum, 2);
                l_r[ri] = l_r[ri] * al + sum;
#pragma unroll
                for (int t = 0; t < 8; t++) {
                    o[mt][t][2 * r] *= al; o[mt][t][2 * r + 1] *= al;
                }
            }

        // ---- O += P V (V row-major, trans ldsm: rows = k, cols = d) ----
#pragma unroll
        for (int ks = 0; ks < 4; ks++) {
            const int t0 = 2 * ks, t1 = 2 * ks + 1;
            uint32_t pa[2][4];
#pragma unroll
            for (int mt = 0; mt < 2; mt++) {
                pa[mt][0] = pack_h(s[mt][t0][0], s[mt][t0][1]);
                pa[mt][1] = pack_h(s[mt][t0][2], s[mt][t0][3]);
                pa[mt][2] = pack_h(s[mt][t1][0], s[mt][t1][1]);
                pa[mt][3] = pack_h(s[mt][t1][2], s[mt][t1][3]);
            }
#pragma unroll
            for (int np = 0; np < 4; np++) {
                uint32_t v4[4];
                const uint32_t base = (uint32_t)(ks * 16) * A_STRIDE_B + np * 32 + v_off;
                ldsm4t(v4, st + A_TILE_B + base);
#pragma unroll
                for (int mt = 0; mt < 2; mt++) {
                    mma_f16(o[mt][2 * np],     pa[mt], v4);
                    mma_f16(o[mt][2 * np + 1], pa[mt], v4 + 2);
                }
            }
        }

        if (it + 2 < 32) load_stage((it + 2) % 3, (it + 2) * 64);
        CP_COMMIT();
    }

    // ---- epilogue: context hi/lo ----
#pragma unroll
    for (int mt = 0; mt < 2; mt++) {
        const float inv0 = 1.f / l_r[mt * 2];
        const float inv1 = 1.f / l_r[mt * 2 + 1];
        const int row0 = q0 + wid * 32 + mt * 16 + (lane >> 2);
#pragma unroll
        for (int t = 0; t < 8; t++) {
            const int col = h * 64 + t * 8 + (lane & 3) * 2;
            store_hilo(CH, CL, (size_t)(b * SEQ + row0) * D_MODEL + col,
                       o[mt][t][0] * inv0, o[mt][t][1] * inv0);
            store_hilo(CH, CL, (size_t)(b * SEQ + row0 + 8) * D_MODEL + col,
                       o[mt][t][2] * inv1, o[mt][t][3] * inv1);
        }
    }
}

// =================================================================================
// launch
// =================================================================================
extern "C" void kernel_launch(void* const* d_in, const int* in_sizes, int n_in,
                              void* d_out, int out_size)
{
    const float* x_q = (const float*)d_in[0];
    const float* x_k = (const float*)d_in[1];
    const float* x_v = (const float*)d_in[2];
    const float* wq  = (const float*)d_in[3];
    const float* bq  = (const float*)d_in[4];
    const float* wk  = (const float*)d_in[5];
    const float* bk  = (const float*)d_in[6];
    const float* wv  = (const float*)d_in[7];
    const float* bv  = (const float*)d_in[8];
    const float* wo  = (const float*)d_in[9];
    const float* bo  = (const float*)d_in[10];
    float* out = (float*)d_out;

    __half *x0, *x1, *x2, *q16, *k16, *v16, *ch, *cl;
    __half *w0, *w1, *w2, *w3;
    cudaGetSymbolAddress((void**)&x0,  g_X0);
    cudaGetSymbolAddress((void**)&x1,  g_X1);
    cudaGetSymbolAddress((void**)&x2,  g_X2);
    cudaGetSymbolAddress((void**)&q16, g_Q16);
    cudaGetSymbolAddress((void**)&k16, g_K16);
    cudaGetSymbolAddress((void**)&v16, g_V16);
    cudaGetSymbolAddress((void**)&ch,  g_CH);
    cudaGetSymbolAddress((void**)&cl,  g_CL);
    cudaGetSymbolAddress((void**)&w0,  g_W0);
    cudaGetSymbolAddress((void**)&w1,  g_W1);
    cudaGetSymbolAddress((void**)&w2,  g_W2);
    cudaGetSymbolAddress((void**)&w3,  g_W3);

    static int attr_set = 0;
    const int proj_smem = 3 * 2 * G_T128;   // 110592
    const int gemf_smem = 2 * 3 * G_T128;   // 110592
    if (!attr_set) {
        cudaFuncSetAttribute(proj3_kernel,
                             cudaFuncAttributeMaxDynamicSharedMemorySize, proj_smem);
        cudaFuncSetAttribute(gemmF_kernel,
                             cudaFuncAttributeMaxDynamicSharedMemorySize, gemf_smem);
        cudaFuncSetAttribute(attention_mma_kernel,
                             cudaFuncAttributeMaxDynamicSharedMemorySize, A_SMEM_TOT);
        attr_set = 1;
    }

    const int NX = M_TOT * D_MODEL;
    const int NW = D_MODEL * D_MODEL;
    dim3 cb(256);

    // converts: inputs (z=3) + all four weights (z=4)
    {
        ConvNArgs cx; cx.src[0] = x_q; cx.src[1] = x_k; cx.src[2] = x_v; cx.src[3] = x_q;
        cx.dst[0] = x0; cx.dst[1] = x1; cx.dst[2] = x2; cx.dst[3] = x0;
        convN_kernel<<<dim3((NX / 4 + 255) / 256, 1, 3), cb>>>(cx, NX);
        ConvNArgs cw; cw.src[0] = wq; cw.src[1] = wk; cw.src[2] = wv; cw.src[3] = wo;
        cw.dst[0] = w0; cw.dst[1] = w1; cw.dst[2] = w2; cw.dst[3] = w3;
        convN_kernel<<<dim3((NW / 4 + 255) / 256, 1, 4), cb>>>(cw, NW);
    }

    // fused QKV projections (fp16 1-term; Q pre-scaled)
    Proj3Args pa;
    pa.p[0] = { x0, w0, bq, q16, 0.125f };
    pa.p[1] = { x1, w1, bk, k16, 1.0f };
    pa.p[2] = { x2, w2, bv, v16, 1.0f };
    proj3_kernel<<<dim3(8, 64, 3), 128, proj_smem>>>(pa);

    // attention (V row-major + trans ldsm; no transpose pass)
    attention_mma_kernel<<<dim3(SEQ / 128, BATCH * NHEAD), 128, A_SMEM_TOT>>>(
        q16, k16, v16, ch, cl);

    // output projection (C hi/lo x W, 2 products)
    gemmF_kernel<<<dim3(8, 64), 128, gemf_smem>>>(ch, cl, w3, bo, out);
}